// round 4
// baseline (speedup 1.0000x reference)
#include <cuda_runtime.h>
#include <cstdint>

// SpatialPool: fm [B=16, C=512, H=38, W=38] f32 (NCHW)
//   -> out [B, H*W, 9*C] f32, out[b, h*W+w, (di*3+dj)*C + c]
//      = fm[b, c, clamp(h+di-1), clamp(w+dj-1)]  (replicate pad)
//
// R3: coalesced spatial-minor LDG, XOR-swizzled smem (conflict-free STS and
// LDS), warp-per-position write phase (each smem pos read once, stored to
// its 1-3 output chunks as coalesced scalar STGs).

namespace {
constexpr int HH   = 38;
constexpr int C    = 512;
constexpr int CSUB = 128;       // channels per CTA
constexpr int NB   = 9;
constexpr int WT   = 19;        // w positions per CTA
constexpr int LW   = WT + 2;    // 21 local cols incl. halo
constexpr int NPOS = 3 * LW;    // 63 smem positions
constexpr int THREADS = 512;
}

__global__ __launch_bounds__(THREADS, 3)
void spatialpool_kernel(const float* __restrict__ fm, float* __restrict__ out) {
    // logical (pos, c) stored at smP[pos*128 + (c ^ (pos & 31))]
    __shared__ float smP[NPOS * CSUB];   // 32,256 B

    const int wh = blockIdx.x & 1;
    const int cg = blockIdx.x >> 1;       // channel group 0..3
    const int w0 = wh * WT;
    const int y  = blockIdx.y;
    const int b  = blockIdx.z;

    const float* __restrict__ fb =
        fm + ((size_t)b * C + (size_t)cg * CSUB) * (HH * HH);

    const int yl0 = max(y - 1, 0);
    const int yl2 = min(y + 1, HH - 1);

    // ---- Load: idx = c*63 + pos (pos minor) -> lanes read contiguous
    // 21-float runs (coalesced LDG). Swizzled STS -> conflict-free. ----
    for (int idx = threadIdx.x; idx < CSUB * NPOS; idx += THREADS) {
        int c   = idx / NPOS;
        int pos = idx - c * NPOS;
        int r   = pos / LW;
        int l   = pos - r * LW;
        int yl  = (r == 0) ? yl0 : ((r == 1) ? y : yl2);
        int xg  = min(max(w0 - 1 + l, 0), HH - 1);
        smP[pos * CSUB + (c ^ (pos & 31))] = fb[c * (HH * HH) + yl * HH + xg];
    }
    __syncthreads();

    // ---- Write: warp per smem position. Read the 128 channels once
    // (4 conflict-free scalar LDS), store to each of the 1-3 output
    // chunks that use this position (coalesced 128B scalar STGs). ----
    const int wid  = threadIdx.x >> 5;
    const int lane = threadIdx.x & 31;
    const size_t rowstride = (size_t)NB * C;   // 4608 floats per (b,y,w)
    const size_t base0 =
        ((size_t)b * (HH * HH) + (size_t)y * HH + w0) * rowstride
        + (size_t)cg * CSUB;

    for (int pos = wid; pos < NPOS; pos += THREADS / 32) {
        int r  = pos / LW;            // = di
        int lp = pos - r * LW;
        int off = lane ^ (pos & 31);
        const float* sp = &smP[pos * CSUB + off];
        float v0 = sp[0];             // channel lane
        float v1 = sp[32];            // channel lane+32
        float v2 = sp[64];
        float v3 = sp[96];

        int djlo = max(0, lp - (WT - 1));
        int djhi = min(2, lp);
        #pragma unroll
        for (int dj = 0; dj < 3; ++dj) {
            if (dj < djlo || dj > djhi) continue;
            int wl = lp - dj;
            int n  = r * 3 + dj;
            float* __restrict__ o =
                out + base0 + (size_t)wl * rowstride + n * C;
            o[lane]      = v0;
            o[lane + 32] = v1;
            o[lane + 64] = v2;
            o[lane + 96] = v3;
        }
    }
}

extern "C" void kernel_launch(void* const* d_in, const int* in_sizes, int n_in,
                              void* d_out, int out_size) {
    const float* fm = (const float*)d_in[0];
    float* out = (float*)d_out;
    (void)in_sizes; (void)n_in; (void)out_size;

    dim3 grid(2 * (C / CSUB), HH, 16);   // (8, 38, 16) = 4864 CTAs
    spatialpool_kernel<<<grid, THREADS>>>(fm, out);
}

// round 5
// speedup vs baseline: 1.0509x; 1.0509x over previous
#include <cuda_runtime.h>
#include <cstdint>

// SpatialPool: fm [B=16, C=512, H=38, W=38] f32 (NCHW)
//   -> out [B, H*W, 9*C] f32, out[b, h*W+w, (di*3+dj)*C + c]
//      = fm[b, c, clamp(h+di-1), clamp(w+dj-1)]  (replicate pad)
//
// R5: coalesced spatial-minor loads (R3) + vectorized conflict-free write
// phase (R2), bridged by a float4-granularity XOR swizzle in smem.
//   smem: logical (pos, c) at smP[pos*128 + 4*((c>>2)^(pos&31)) + (c&3)]
//   - load STS: 4-way conflict, but only 252 STS/CTA (negligible)
//   - write LDS.128: conflict-free, STG.128 coalesced 512B chunks

namespace {
constexpr int HH   = 38;
constexpr int C    = 512;
constexpr int CSUB = 128;       // channels per CTA
constexpr int NB   = 9;
constexpr int WT   = 19;        // w positions per CTA
constexpr int LW   = WT + 2;    // 21 local cols incl. halo
constexpr int NPOS = 3 * LW;    // 63 smem positions
constexpr int THREADS = 512;
}

__global__ __launch_bounds__(THREADS, 3)
void spatialpool_kernel(const float* __restrict__ fm, float* __restrict__ out) {
    __shared__ float smP[NPOS * CSUB];   // 32,256 B

    const int wh = blockIdx.x & 1;
    const int cg = blockIdx.x >> 1;       // channel group 0..3
    const int w0 = wh * WT;
    const int y  = blockIdx.y;
    const int b  = blockIdx.z;

    const float* __restrict__ fb =
        fm + ((size_t)b * C + (size_t)cg * CSUB) * (HH * HH);

    const int yl0 = max(y - 1, 0);
    const int yl2 = min(y + 1, HH - 1);

    // ---- Load: idx = c*64 + p (p minor, padded to 64) -> lanes cover
    // consecutive spatial positions -> coalesced LDG. Swizzled STS. ----
    #pragma unroll
    for (int it = 0; it < (CSUB * 64) / THREADS; ++it) {
        int idx = it * THREADS + threadIdx.x;
        int c = idx >> 6;
        int p = idx & 63;
        if (p < NPOS) {
            int r  = (p >= 2 * LW) ? 2 : ((p >= LW) ? 1 : 0);
            int l  = p - r * LW;
            int yl = (r == 0) ? yl0 : ((r == 1) ? y : yl2);
            int xg = min(max(w0 - 1 + l, 0), HH - 1);
            int sw = (p << 7) + ((((c >> 2) ^ (p & 31)) << 2) | (c & 3));
            smP[sw] = fb[c * (HH * HH) + yl * HH + xg];
        }
    }
    __syncthreads();

    // ---- Write: warp-per-chunk, chunk = (wl, n) = 128 floats.
    // Each lane: one conflict-free LDS.128 + one coalesced STG.128. ----
    const int wid  = threadIdx.x >> 5;
    const int lane = threadIdx.x & 31;
    float4* __restrict__ out4 = (float4*)out;
    const size_t rowbase =
        ((size_t)b * (HH * HH) + (size_t)y * HH + w0) * (size_t)(NB * C / 4)
        + (size_t)cg * (CSUB / 4);

    for (int tch = wid; tch < WT * NB; tch += THREADS / 32) {
        int wl = tch / NB;
        int n  = tch - wl * NB;
        int di = (n >= 6) ? 2 : ((n >= 3) ? 1 : 0);
        int pos = 18 * di + n + wl;        // = di*LW + (wl + dj)

        const float4 v = *(const float4*)
            &smP[(pos << 7) + ((lane ^ (pos & 31)) << 2)];
        out4[rowbase + (size_t)wl * (NB * C / 4) + n * (C / 4) + lane] = v;
    }
}

extern "C" void kernel_launch(void* const* d_in, const int* in_sizes, int n_in,
                              void* d_out, int out_size) {
    const float* fm = (const float*)d_in[0];
    float* out = (float*)d_out;
    (void)in_sizes; (void)n_in; (void)out_size;

    dim3 grid(2 * (C / CSUB), HH, 16);   // (8, 38, 16) = 4864 CTAs
    spatialpool_kernel<<<grid, THREADS>>>(fm, out);
}

// round 6
// speedup vs baseline: 1.4932x; 1.4209x over previous
#include <cuda_runtime.h>
#include <cstdint>

// SpatialPool: fm [B=16, C=512, H=38, W=38] f32 (NCHW)
//   -> out [B, H*W, 9*C] f32, out[b, h*W+w, (di*3+dj)*C + c]
//      = fm[b, c, clamp(h+di-1), clamp(w+dj-1)]  (replicate pad)
//
// R6: cp.async load phase (no LDG->STS register dependency: latency hidden),
// 2 output rows per CTA (halves vertical halo re-read), float4-swizzled smem,
// R2-style vectorized conflict-free write phase (LDS.128 + 512B STG.128).

namespace {
constexpr int HH   = 38;
constexpr int C    = 512;
constexpr int CSUB = 128;        // channels per CTA
constexpr int NCG  = C / CSUB;   // 4
constexpr int NB   = 9;
constexpr int WT   = 19;         // w positions per CTA
constexpr int LW   = WT + 2;     // 21 local cols incl. halo
constexpr int NY   = 2;          // output rows per CTA
constexpr int NR   = NY + 2;     // 4 loaded rows incl. halo
constexpr int NPOS = NR * LW;    // 84 smem positions
constexpr int THREADS = 512;
constexpr int CHUNKS = NY * WT * NB;   // 342 write chunks per CTA
}

__device__ __forceinline__ void cp_async4(float* smem_dst, const float* gsrc) {
    uint32_t sa = (uint32_t)__cvta_generic_to_shared(smem_dst);
    asm volatile("cp.async.ca.shared.global [%0], [%1], 4;\n"
                 :: "r"(sa), "l"(gsrc) : "memory");
}

__global__ __launch_bounds__(THREADS, 3)
void spatialpool_kernel(const float* __restrict__ fm, float* __restrict__ out) {
    // logical (pos, c) at smP[pos*128 + 4*((c>>2)^(pos&31)) + (c&3)]
    __shared__ float smP[NPOS * CSUB];   // 43,008 B -> 3 CTAs/SM

    const int wh = blockIdx.x & 1;
    const int cg = blockIdx.x >> 1;        // channel group 0..3
    const int w0 = wh * WT;
    const int y0 = blockIdx.y * NY;        // first output row
    const int b  = blockIdx.z;

    const float* __restrict__ fb =
        fm + ((size_t)b * C + (size_t)cg * CSUB) * (HH * HH);

    // ---- Load: 21 guard-free cp.async per thread (84*128 = 21*512).
    // Lanes sweep p (spatial-minor) -> coalesced 21-float runs. ----
    #pragma unroll
    for (int it = 0; it < (NPOS * CSUB) / THREADS; ++it) {
        int idx = it * THREADS + threadIdx.x;
        int c = idx / NPOS;
        int p = idx - c * NPOS;
        int r = p / LW;
        int l = p - r * LW;
        int yl = min(max(y0 - 1 + r, 0), HH - 1);
        int xg = min(max(w0 - 1 + l, 0), HH - 1);
        int sw = (p << 7) + ((((c >> 2) ^ (p & 31)) << 2) | (c & 3));
        cp_async4(&smP[sw], &fb[c * (HH * HH) + yl * HH + xg]);
    }
    asm volatile("cp.async.wait_all;\n" ::: "memory");
    __syncthreads();

    // ---- Write: warp-per-chunk, chunk = (o, wl, n) = 128 floats.
    // One conflict-free LDS.128 + one coalesced STG.128 per lane. ----
    const int wid  = threadIdx.x >> 5;
    const int lane = threadIdx.x & 31;
    float4* __restrict__ out4 = (float4*)out;
    const size_t rowbase =
        ((size_t)b * (HH * HH) + (size_t)y0 * HH + w0) * (size_t)(NB * C / 4)
        + (size_t)cg * (CSUB / 4);

    for (int tch = wid; tch < CHUNKS; tch += THREADS / 32) {
        int o  = (tch >= WT * NB) ? 1 : 0;       // output row within pair
        int t  = tch - o * (WT * NB);
        int wl = t / NB;
        int n  = t - wl * NB;
        int di = (n >= 6) ? 2 : ((n >= 3) ? 1 : 0);
        int pos = LW * o + 18 * di + wl + n;     // (o+di)*21 + wl + dj

        const float4 v = *(const float4*)
            &smP[(pos << 7) + ((lane ^ (pos & 31)) << 2)];
        out4[rowbase
             + (size_t)o  * (HH * NB * C / 4)
             + (size_t)wl * (NB * C / 4)
             + n * (C / 4) + lane] = v;
    }
}

extern "C" void kernel_launch(void* const* d_in, const int* in_sizes, int n_in,
                              void* d_out, int out_size) {
    const float* fm = (const float*)d_in[0];
    float* out = (float*)d_out;
    (void)in_sizes; (void)n_in; (void)out_size;

    dim3 grid(2 * NCG, HH / NY, 16);   // (8, 19, 16) = 2432 CTAs
    spatialpool_kernel<<<grid, THREADS>>>(fm, out);
}

// round 7
// speedup vs baseline: 1.5448x; 1.0346x over previous
#include <cuda_runtime.h>
#include <cstdint>

// SpatialPool: fm [B=16, C=512, H=38, W=38] f32 (NCHW)
//   -> out [B, H*W, 9*C] f32, out[b, h*W+w, (di*3+dj)*C + c]
//      = fm[b, c, clamp(h+di-1), clamp(w+dj-1)]  (replicate pad)
//
// R7: R6 (cp.async + swizzled smem + vector write) with strength-reduced
// indexing: load phase reuses per-position offsets across 8 channels
// (global channel stride folded into LDGSTS immediates), write phase is
// n-major so di/dj/n*128 are compile-time. launch_bounds(512,4) for
// 64-warp occupancy; streaming stores (.cs) keep input L2-resident.

namespace {
constexpr int HH   = 38;
constexpr int C    = 512;
constexpr int CSUB = 128;        // channels per CTA
constexpr int NCG  = C / CSUB;   // 4
constexpr int NB   = 9;
constexpr int WT   = 19;         // w positions per CTA
constexpr int LW   = WT + 2;     // 21 local cols incl. halo
constexpr int NY   = 2;          // output rows per CTA
constexpr int NR   = NY + 2;     // 4 loaded rows incl. halo
constexpr int NPOS = NR * LW;    // 84 smem positions
constexpr int THREADS = 512;
constexpr int HW   = HH * HH;    // 1444
constexpr int RS4  = NB * C / 4; // 1152 float4 per (b,y,w)
constexpr int YS4  = HH * RS4;   // float4 stride for y+1
}

__device__ __forceinline__ void cp_async4(float* smem_dst, const float* gsrc) {
    uint32_t sa = (uint32_t)__cvta_generic_to_shared(smem_dst);
    asm volatile("cp.async.ca.shared.global [%0], [%1], 4;\n"
                 :: "r"(sa), "l"(gsrc) : "memory");
}

__global__ __launch_bounds__(THREADS, 4)
void spatialpool_kernel(const float* __restrict__ fm, float* __restrict__ out) {
    // logical (pos, c) at smP[pos*128 + 4*((c>>2)^(pos&31)) + (c&3)]
    __shared__ float smP[NPOS * CSUB];   // 43,008 B

    const int lane = threadIdx.x & 31;
    const int wid  = threadIdx.x >> 5;

    const int wh = blockIdx.x & 1;
    const int cg = blockIdx.x >> 1;        // channel group 0..3
    const int w0 = wh * WT;
    const int y0 = blockIdx.y * NY;        // first output row
    const int b  = blockIdx.z;

    const float* __restrict__ fb =
        fm + ((size_t)b * C + (size_t)cg * CSUB) * HW;

    // ---- Load: thread owns p = lane + 32k (k<3), sweeps c = wid + 16m.
    // Offset computed once per p; channel stride is a compile-time
    // immediate. Lanes sweep consecutive p -> coalesced. ----
    {
        const float* __restrict__ fc = fb + (size_t)wid * HW;  // c0 = wid
        const int c3  = wid & 3;
        const int cq0 = wid >> 2;
        #pragma unroll
        for (int k = 0; k < 3; ++k) {
            int p = lane + 32 * k;
            if (k == 2 && p >= NPOS) break;
            int r  = p / LW;
            int l  = p - r * LW;
            int yl = min(max(y0 - 1 + r, 0), HH - 1);
            int xg = min(max(w0 - 1 + l, 0), HH - 1);
            const float* __restrict__ g = fc + yl * HH + xg;
            const int swk = (p << 7) + c3;
            #pragma unroll
            for (int m = 0; m < 8; ++m) {
                int sw = swk + (((cq0 + 4 * m) ^ lane) << 2);
                cp_async4(&smP[sw], g + m * 16 * HW);
            }
        }
    }
    asm volatile("cp.async.wait_all;\n" ::: "memory");
    __syncthreads();

    // ---- Write: n-major warp-per-chunk. di/dj/n*128 compile-time.
    // One conflict-free LDS.128 + one coalesced STG.128 (streaming). ----
    float4* __restrict__ out4 = (float4*)out;
    const size_t rowbase =
        ((size_t)b * HW + (size_t)y0 * HH + w0) * (size_t)RS4
        + (size_t)cg * (CSUB / 4) + lane;

    #pragma unroll
    for (int n = 0; n < NB; ++n) {
        const int di = n / 3;
        const int dj = n - di * 3;
        #pragma unroll 3
        for (int q = wid; q < NY * WT; q += THREADS / 32) {
            int o   = (q >= WT) ? 1 : 0;
            int wl  = q - WT * o;
            int pos = (o + di) * LW + wl + dj;

            const float4 v = *(const float4*)
                &smP[(pos << 7) + ((lane ^ (pos & 31)) << 2)];
            __stcs(&out4[rowbase + (size_t)o * YS4
                         + (size_t)wl * RS4 + n * (C / 4)], v);
        }
    }
}

extern "C" void kernel_launch(void* const* d_in, const int* in_sizes, int n_in,
                              void* d_out, int out_size) {
    const float* fm = (const float*)d_in[0];
    float* out = (float*)d_out;
    (void)in_sizes; (void)n_in; (void)out_size;

    dim3 grid(2 * NCG, HH / NY, 16);   // (8, 19, 16) = 2432 CTAs
    spatialpool_kernel<<<grid, THREADS>>>(fm, out);
}